// round 5
// baseline (speedup 1.0000x reference)
#include <cuda_runtime.h>
#include <cuda_bf16.h>
#include <math.h>
#include <stdint.h>

// Problem constants
#define BB 2
#define SS 2048
#define DD 1024
#define NH 16
#define RR (BB*SS)          // 4096 rows
#define QKVW (3*DD)         // 3072

// ------------------------- scratch (static device memory) -------------------------
__device__ float g_h  [(size_t)RR*DD];
__device__ float g_h2 [(size_t)RR*DD];
__device__ float g_t  [(size_t)RR*DD];
__device__ float g_qkv[(size_t)RR*QKVW];
__device__ float g_ao [(size_t)RR*DD];
__device__ float g_cs [SS*16];
__device__ float g_sn [SS*16];

#define BFA __device__ __align__(16) __nv_bfloat16
BFA g_xhi [(size_t)RR*DD];  BFA g_xlo [(size_t)RR*DD];
BFA g_hhi [(size_t)RR*DD];  BFA g_hlo [(size_t)RR*DD];
BFA g_aohi[(size_t)RR*DD];  BFA g_aolo[(size_t)RR*DD];
BFA g_h2hi[(size_t)RR*DD];  BFA g_h2lo[(size_t)RR*DD];
BFA g_thi [(size_t)RR*DD];  BFA g_tlo [(size_t)RR*DD];
BFA g_winThi [(size_t)DD*DD];    BFA g_winTlo [(size_t)DD*DD];
BFA g_wqkvThi[(size_t)QKVW*DD];  BFA g_wqkvTlo[(size_t)QKVW*DD];
BFA g_woutThi[(size_t)DD*DD];    BFA g_woutTlo[(size_t)DD*DD];
BFA g_w1Thi  [(size_t)DD*DD];    BFA g_w1Tlo  [(size_t)DD*DD];
BFA g_w2Thi  [(size_t)DD*DD];    BFA g_w2Tlo  [(size_t)DD*DD];

// ------------------------- base-ISA helpers (sm_103 base target) ------------------
__device__ __forceinline__ uint32_t smem_u32(const void* p) {
    uint32_t a;
    asm("{ .reg .u64 t; cvta.to.shared.u64 t, %1; cvt.u32.u64 %0, t; }" : "=r"(a) : "l"(p));
    return a;
}
__device__ __forceinline__ uint32_t swz(uint32_t off) { return off ^ ((off >> 3) & 0x70); }

#define CP16(dst, src) \
    asm volatile("cp.async.cg.shared.global [%0], [%1], 16;" :: "r"(dst), "l"(src))
#define CP_COMMIT() asm volatile("cp.async.commit_group;" ::: "memory")
#define CP_WAIT(n)  asm volatile("cp.async.wait_group %0;" :: "n"(n) : "memory")

__device__ __forceinline__ void ldsm4(uint32_t* r, uint32_t addr) {
    asm volatile("ldmatrix.sync.aligned.m8n8.x4.shared.b16 {%0,%1,%2,%3}, [%4];"
        : "=r"(r[0]), "=r"(r[1]), "=r"(r[2]), "=r"(r[3]) : "r"(addr));
}
__device__ __forceinline__ void mma_bf16(float* c, const uint32_t* a, const uint32_t* b) {
    asm volatile("mma.sync.aligned.m16n8k16.row.col.f32.bf16.bf16.f32 "
        "{%0,%1,%2,%3}, {%4,%5,%6,%7}, {%8,%9}, {%0,%1,%2,%3};"
        : "+f"(c[0]), "+f"(c[1]), "+f"(c[2]), "+f"(c[3])
        : "r"(a[0]), "r"(a[1]), "r"(a[2]), "r"(a[3]), "r"(b[0]), "r"(b[1]));
}

// ------------------------- fp32 -> bf16 hi/lo split helpers -----------------------
__device__ __forceinline__ void split2(float v, __nv_bfloat16& hi, __nv_bfloat16& lo) {
    hi = __float2bfloat16(v);
    lo = __float2bfloat16(v - __bfloat162float(hi));
}

// ------------------------- converts ------------------------------------------------
__global__ void conv_hilo_kernel(const float4* __restrict__ in,
                                 __nv_bfloat162* __restrict__ hi,
                                 __nv_bfloat162* __restrict__ lo, int n4)
{
    int i = blockIdx.x * blockDim.x + threadIdx.x;
    if (i >= n4) return;
    float4 v = in[i];
    __nv_bfloat16 h0, l0, h1, l1, h2, l2, h3, l3;
    split2(v.x, h0, l0); split2(v.y, h1, l1); split2(v.z, h2, l2); split2(v.w, h3, l3);
    hi[2*i]   = __nv_bfloat162(h0, h1);  hi[2*i+1] = __nv_bfloat162(h2, h3);
    lo[2*i]   = __nv_bfloat162(l0, l1);  lo[2*i+1] = __nv_bfloat162(l2, l3);
}

// W[K,N] fp32 -> T[N,K] bf16 hi/lo (transpose)
__global__ void convT_kernel(const float* __restrict__ W,
                             __nv_bfloat16* __restrict__ Thi, __nv_bfloat16* __restrict__ Tlo,
                             int K, int N)
{
    __shared__ float tile[32][33];
    const int n0 = blockIdx.x * 32, k0 = blockIdx.y * 32;
    const int tx = threadIdx.x, ty = threadIdx.y;
    #pragma unroll
    for (int j = 0; j < 32; j += 8)
        tile[ty + j][tx] = W[(size_t)(k0 + ty + j) * N + n0 + tx];
    __syncthreads();
    #pragma unroll
    for (int j = 0; j < 32; j += 8) {
        float v = tile[tx][ty + j];
        __nv_bfloat16 hb, lb; split2(v, hb, lb);
        size_t o = (size_t)(n0 + ty + j) * K + k0 + tx;
        Thi[o] = hb; Tlo[o] = lb;
    }
}

// ------------------------- mma.sync GEMM -------------------------------------------
// C[M,N] = Ahi/lo[M,K] @ (Bhi/lo[N,K])^T + bias (+resid)(+silu); 3-pass bf16 split.
#define GBK 64
#define STAGE_BYTES 65536           // 4 matrices x (128 rows x 128 bytes)
#define GEMM_SMEM (1024 + 2*STAGE_BYTES)

__device__ __forceinline__ void issue_stage(uint32_t st32,
    const __nv_bfloat16* __restrict__ Ahi, const __nv_bfloat16* __restrict__ Alo,
    const __nv_bfloat16* __restrict__ Bhi, const __nv_bfloat16* __restrict__ Blo,
    int m0, int n0, int k0, int K, int tid)
{
    #pragma unroll
    for (int it = 0; it < 16; it++) {
        int u = tid + it * 256;
        int mat = u >> 10;            // 0:Ah 1:Al 2:Bh 3:Bl
        int w = u & 1023;
        int row = w >> 3;
        int c16 = w & 7;
        const __nv_bfloat16* src;
        int grow;
        if (mat == 0)      { src = Ahi; grow = m0 + row; }
        else if (mat == 1) { src = Alo; grow = m0 + row; }
        else if (mat == 2) { src = Bhi; grow = n0 + row; }
        else               { src = Blo; grow = n0 + row; }
        uint32_t off = swz((uint32_t)(row * 128 + c16 * 16));
        CP16(st32 + (mat << 14) + off,
             (const void*)(src + (size_t)grow * K + k0 + c16 * 8));
    }
}

template<bool SILU, bool RESID, bool EMIT, bool WF32>
__global__ __launch_bounds__(256)
void mma_gemm(const __nv_bfloat16* __restrict__ Ahi, const __nv_bfloat16* __restrict__ Alo,
              const __nv_bfloat16* __restrict__ Bhi, const __nv_bfloat16* __restrict__ Blo,
              const float* __restrict__ bias, const float* __restrict__ resid,
              float* __restrict__ C, __nv_bfloat16* __restrict__ Chi, __nv_bfloat16* __restrict__ Clo,
              int M, int N, int K)
{
    extern __shared__ char smem_raw[];
    const uint32_t raw32 = smem_u32(smem_raw);
    const uint32_t base32 = (raw32 + 1023u) & ~1023u;

    const int tid = threadIdx.x;
    const int lane = tid & 31;
    const int wid = tid >> 5;
    const int wm = wid & 3;            // 4 warps along M
    const int wn = wid >> 2;           // 2 warps along N
    const int m0 = blockIdx.y * 128;
    const int n0 = blockIdx.x * 128;

    float acc[2][8][4];
    #pragma unroll
    for (int mt = 0; mt < 2; mt++)
        #pragma unroll
        for (int nt = 0; nt < 8; nt++)
            #pragma unroll
            for (int q = 0; q < 4; q++) acc[mt][nt][q] = 0.f;

    const int NK = K / GBK;            // 16
    issue_stage(base32, Ahi, Alo, Bhi, Blo, m0, n0, 0, K, tid);
    CP_COMMIT();

    // precomputed intra-tile offsets
    const uint32_t aoff0 = (uint32_t)((wm * 32 + (lane & 15)) * 128 + ((lane >> 4) & 1) * 16);
    const uint32_t boff0 = (uint32_t)((wn * 64 + (lane & 7) + ((lane >> 4) & 1) * 8) * 128
                                      + ((lane >> 3) & 1) * 16);

    for (int i = 0; i < NK; i++) {
        const uint32_t cur32 = base32 + (uint32_t)(i & 1) * STAGE_BYTES;
        if (i + 1 < NK) {
            issue_stage(base32 + (uint32_t)((i + 1) & 1) * STAGE_BYTES,
                        Ahi, Alo, Bhi, Blo, m0, n0, (i + 1) * GBK, K, tid);
            CP_COMMIT();
            CP_WAIT(1);
        } else {
            CP_WAIT(0);
        }
        __syncthreads();

        #pragma unroll
        for (int ks = 0; ks < 4; ks++) {
            const uint32_t ka = aoff0 + ks * 32;
            const uint32_t kb = boff0 + ks * 32;
            uint32_t ah[2][4], al[2][4], bq[4][4];
            ldsm4(ah[0], cur32 + swz(ka));
            ldsm4(ah[1], cur32 + swz(ka + 16 * 128));
            ldsm4(al[0], cur32 + 16384 + swz(ka));
            ldsm4(al[1], cur32 + 16384 + swz(ka + 16 * 128));
            #pragma unroll
            for (int g = 0; g < 4; g++)
                ldsm4(bq[g], cur32 + 32768 + swz(kb + g * 16 * 128));

            // pass 1: Ah * Bh
            #pragma unroll
            for (int mt = 0; mt < 2; mt++)
                #pragma unroll
                for (int nt = 0; nt < 8; nt++)
                    mma_bf16(acc[mt][nt], ah[mt], &bq[nt >> 1][(nt & 1) * 2]);
            // pass 2: Al * Bh
            #pragma unroll
            for (int mt = 0; mt < 2; mt++)
                #pragma unroll
                for (int nt = 0; nt < 8; nt++)
                    mma_bf16(acc[mt][nt], al[mt], &bq[nt >> 1][(nt & 1) * 2]);
            // reload B with lo part
            #pragma unroll
            for (int g = 0; g < 4; g++)
                ldsm4(bq[g], cur32 + 49152 + swz(kb + g * 16 * 128));
            // pass 3: Ah * Bl
            #pragma unroll
            for (int mt = 0; mt < 2; mt++)
                #pragma unroll
                for (int nt = 0; nt < 8; nt++)
                    mma_bf16(acc[mt][nt], ah[mt], &bq[nt >> 1][(nt & 1) * 2]);
        }
        __syncthreads();
    }

    // ------- epilogue -------
    #pragma unroll
    for (int mt = 0; mt < 2; mt++) {
        #pragma unroll
        for (int half = 0; half < 2; half++) {
            const int row = m0 + wm * 32 + mt * 16 + (lane >> 2) + half * 8;
            #pragma unroll
            for (int nt = 0; nt < 8; nt++) {
                const int col = n0 + wn * 64 + nt * 8 + (lane & 3) * 2;
                float v0 = acc[mt][nt][half * 2]     + bias[col];
                float v1 = acc[mt][nt][half * 2 + 1] + bias[col + 1];
                const size_t o = (size_t)row * N + col;
                if (RESID) { v0 += resid[o]; v1 += resid[o + 1]; }
                if (SILU)  { v0 = v0 / (1.f + expf(-v0)); v1 = v1 / (1.f + expf(-v1)); }
                if (WF32)  { *(float2*)(C + o) = make_float2(v0, v1); }
                if (EMIT) {
                    __nv_bfloat16 h0, l0, h1, l1;
                    split2(v0, h0, l0); split2(v1, h1, l1);
                    *(__nv_bfloat162*)(Chi + o) = __nv_bfloat162(h0, h1);
                    *(__nv_bfloat162*)(Clo + o) = __nv_bfloat162(l0, l1);
                }
            }
        }
    }
}

// ------------------------- row L2-norm scale (+optional hi/lo emit) ---------------
template<bool EMIT>
__global__ __launch_bounds__(256)
void l2norm_kernel(const float* __restrict__ x, const float* __restrict__ w,
                   float* __restrict__ out,
                   __nv_bfloat16* __restrict__ ohi, __nv_bfloat16* __restrict__ olo)
{
    const int row = blockIdx.x;
    const int tid = threadIdx.x;
    const float* xr = x + (size_t)row * DD;

    float4 v = *(const float4*)(xr + tid * 4);
    float ss = v.x*v.x + v.y*v.y + v.z*v.z + v.w*v.w;

    __shared__ float red[8];
    __shared__ float inv_s;
    #pragma unroll
    for (int o = 16; o > 0; o >>= 1) ss += __shfl_xor_sync(0xffffffffu, ss, o);
    if ((tid & 31) == 0) red[tid >> 5] = ss;
    __syncthreads();
    if (tid < 32) {
        float t = (tid < 8) ? red[tid] : 0.f;
        #pragma unroll
        for (int o = 4; o > 0; o >>= 1) t += __shfl_xor_sync(0xffffffffu, t, o);
        if (tid == 0) inv_s = 1.f / (sqrtf(t) + 1e-8f);
    }
    __syncthreads();

    const float inv = inv_s;
    float4 wv = *(const float4*)(w + tid * 4);
    float4 o4 = make_float4(wv.x*v.x*inv, wv.y*v.y*inv, wv.z*v.z*inv, wv.w*v.w*inv);
    *(float4*)(out + (size_t)row * DD + tid * 4) = o4;
    if (EMIT) {
        __nv_bfloat16 h0,l0,h1,l1,h2,l2,h3,l3;
        split2(o4.x,h0,l0); split2(o4.y,h1,l1); split2(o4.z,h2,l2); split2(o4.w,h3,l3);
        size_t ob = (size_t)row * DD + tid * 4;
        *(__nv_bfloat162*)(ohi + ob)     = __nv_bfloat162(h0, h1);
        *(__nv_bfloat162*)(ohi + ob + 2) = __nv_bfloat162(h2, h3);
        *(__nv_bfloat162*)(olo + ob)     = __nv_bfloat162(l0, l1);
        *(__nv_bfloat162*)(olo + ob + 2) = __nv_bfloat162(l2, l3);
    }
}

// ------------------------- RoPE ----------------------------------------------------
__global__ void rope_table_kernel(float* __restrict__ cs, float* __restrict__ sn)
{
    int idx = blockIdx.x * blockDim.x + threadIdx.x;
    if (idx >= SS * 16) return;
    int i = idx & 15, pos = idx >> 4;
    double inv = 1.0 / pow(10000.0, (double)(2*i) / 32.0);
    double ang = (double)pos * inv;
    cs[idx] = (float)cos(ang);
    sn[idx] = (float)sin(ang);
}

__global__ void rope_apply_kernel(float* __restrict__ qkv,
                                  const float* __restrict__ cs,
                                  const float* __restrict__ sn)
{
    int idx = blockIdx.x * blockDim.x + threadIdx.x;
    if (idx >= RR * NH * 16) return;
    const int i   = idx & 15;
    const int h   = (idx >> 4) & 15;
    const int row = idx >> 8;
    const int s   = row & (SS - 1);

    const float c  = cs[s*16 + i];
    const float sv = sn[s*16 + i];

    float* base = qkv + (size_t)row * QKVW + h*192 + 2*i;
    float2 q = *(float2*)base;
    *(float2*)base = make_float2(q.x*c - q.y*sv, q.y*c + q.x*sv);
    float2 k = *(float2*)(base + 64);
    *(float2*)(base + 64) = make_float2(k.x*c - k.y*sv, k.y*c + k.x*sv);
}

// ------------------------- fused attention (linear log-softmax trick) -------------
__global__ __launch_bounds__(256)
void attn_kernel(const float* __restrict__ qkv, const float* __restrict__ mask,
                 float* __restrict__ ao,
                 __nv_bfloat16* __restrict__ aohi, __nv_bfloat16* __restrict__ aolo)
{
    const int bh = blockIdx.y;
    const int b = bh >> 4, h = bh & 15;
    const int s0 = blockIdx.x * 64;
    const int tid = threadIdx.x;

    __shared__ float Qs[64][65];
    __shared__ float Ks[32][65];
    __shared__ float Vs[32][65];
    __shared__ float Sx[64][33];
    __shared__ float sm[64], sl[64], svs[64];

    for (int i = tid; i < 64*16; i += 256) {
        int r = i >> 4, c4 = (i & 15) << 2;
        float4 v = *(const float4*)(qkv + (size_t)(b*SS + s0 + r)*QKVW + h*192 + c4);
        Qs[r][c4] = v.x; Qs[r][c4+1] = v.y; Qs[r][c4+2] = v.z; Qs[r][c4+3] = v.w;
    }
    if (tid < 64) { sm[tid] = -INFINITY; sl[tid] = 0.f; svs[tid] = 0.f; }
    __syncthreads();

    float acc[4][4];
    #pragma unroll
    for (int i = 0; i < 4; i++)
        #pragma unroll
        for (int j = 0; j < 4; j++) acc[i][j] = 0.f;

    const int txs = tid & 7,  tys = tid >> 3;
    const int txa = tid & 15, tya = tid >> 4;
    const float scale = 0.125f;
    const float* maskb = mask + (size_t)b * SS * SS;

    for (int t0 = 0; t0 < SS; t0 += 32) {
        for (int i = tid; i < 32*16; i += 256) {
            int r = i >> 4, c4 = (i & 15) << 2;
            size_t base = (size_t)(b*SS + t0 + r)*QKVW + h*192;
            float4 kv = *(const float4*)(qkv + base + 64 + c4);
            Ks[r][c4] = kv.x; Ks[r][c4+1] = kv.y; Ks[r][c4+2] = kv.z; Ks[r][c4+3] = kv.w;
            float4 vv = *(const float4*)(qkv + base + 128 + c4);
            Vs[r][c4] = vv.x; Vs[r][c4+1] = vv.y; Vs[r][c4+2] = vv.z; Vs[r][c4+3] = vv.w;
        }
        __syncthreads();

        float sreg[2][4];
        #pragma unroll
        for (int i = 0; i < 2; i++)
            #pragma unroll
            for (int j = 0; j < 4; j++) sreg[i][j] = 0.f;

        #pragma unroll 8
        for (int kk = 0; kk < 64; kk++) {
            float q0 = Qs[tys*2][kk], q1 = Qs[tys*2+1][kk];
            #pragma unroll
            for (int j = 0; j < 4; j++) {
                float kvv = Ks[txs*4 + j][kk];
                sreg[0][j] += q0 * kvv;
                sreg[1][j] += q1 * kvv;
            }
        }
        #pragma unroll
        for (int i = 0; i < 2; i++) {
            int r = tys*2 + i;
            float4 mk = *(const float4*)(maskb + (size_t)(s0 + r)*SS + t0 + txs*4);
            Sx[r][txs*4+0] = sreg[i][0]*scale + mk.x;
            Sx[r][txs*4+1] = sreg[i][1]*scale + mk.y;
            Sx[r][txs*4+2] = sreg[i][2]*scale + mk.z;
            Sx[r][txs*4+3] = sreg[i][3]*scale + mk.w;
        }
        __syncthreads();

        if (tid < 64) {
            const int r = tid;
            float mx = sm[r];
            float tmax = -INFINITY;
            #pragma unroll 8
            for (int j = 0; j < 32; j++) tmax = fmaxf(tmax, Sx[r][j]);
            float nm = fmaxf(mx, tmax);
            float l = sl[r] * __expf(mx - nm);
            #pragma unroll 8
            for (int j = 0; j < 32; j++) l += __expf(Sx[r][j] - nm);
            sm[r] = nm; sl[r] = l;
        } else if (tid < 128) {
            const int d = tid - 64;
            float s = 0.f;
            #pragma unroll 8
            for (int r = 0; r < 32; r++) s += Vs[r][d];
            svs[d] += s;
        }

        #pragma unroll 4
        for (int kk = 0; kk < 32; kk++) {
            float sv[4];
            #pragma unroll
            for (int i = 0; i < 4; i++) sv[i] = Sx[tya*4 + i][kk];
            #pragma unroll
            for (int j = 0; j < 4; j++) {
                float vv = Vs[kk][txa*4 + j];
                #pragma unroll
                for (int i = 0; i < 4; i++) acc[i][j] += sv[i] * vv;
            }
        }
        __syncthreads();
    }

    #pragma unroll
    for (int i = 0; i < 4; i++) {
        const int r = tya*4 + i;
        const float lse = sm[r] + logf(sl[r]);
        const size_t ob = (size_t)(b*SS + s0 + r)*DD + h*64;
        #pragma unroll
        for (int j = 0; j < 4; j++) {
            const int d = txa*4 + j;
            float v = acc[i][j] - lse * svs[d];
            ao[ob + d] = v;
            __nv_bfloat16 hb, lb; split2(v, hb, lb);
            aohi[ob + d] = hb; aolo[ob + d] = lb;
        }
    }
}

// ------------------------- launch -------------------------------------------------
extern "C" void kernel_launch(void* const* d_in, const int* in_sizes, int n_in,
                              void* d_out, int out_size)
{
    const float* x      = (const float*)d_in[0];
    const float* mask   = (const float*)d_in[1];
    const float* Win    = (const float*)d_in[2];
    const float* bin    = (const float*)d_in[3];
    const float* attn_w = (const float*)d_in[4];
    const float* Wqkv   = (const float*)d_in[5];
    const float* bqkv   = (const float*)d_in[6];
    const float* Wout   = (const float*)d_in[7];
    const float* bout   = (const float*)d_in[8];
    const float* W1     = (const float*)d_in[9];
    const float* b1     = (const float*)d_in[10];
    const float* W2     = (const float*)d_in[11];
    const float* b2     = (const float*)d_in[12];
    const float* ffn_w  = (const float*)d_in[13];
    float* out = (float*)d_out;

    float *h, *h2, *t, *qkv, *ao, *cs, *sn;
    cudaGetSymbolAddress((void**)&h,   g_h);
    cudaGetSymbolAddress((void**)&h2,  g_h2);
    cudaGetSymbolAddress((void**)&t,   g_t);
    cudaGetSymbolAddress((void**)&qkv, g_qkv);
    cudaGetSymbolAddress((void**)&ao,  g_ao);
    cudaGetSymbolAddress((void**)&cs,  g_cs);
    cudaGetSymbolAddress((void**)&sn,  g_sn);

    __nv_bfloat16 *xhi,*xlo,*hhi,*hlo,*aohi,*aolo,*h2hi,*h2lo,*thi,*tlo;
    __nv_bfloat16 *winThi,*winTlo,*wqkvThi,*wqkvTlo,*woutThi,*woutTlo,*w1Thi,*w1Tlo,*w2Thi,*w2Tlo;
    cudaGetSymbolAddress((void**)&xhi, g_xhi);   cudaGetSymbolAddress((void**)&xlo, g_xlo);
    cudaGetSymbolAddress((void**)&hhi, g_hhi);   cudaGetSymbolAddress((void**)&hlo, g_hlo);
    cudaGetSymbolAddress((void**)&aohi, g_aohi); cudaGetSymbolAddress((void**)&aolo, g_aolo);
    cudaGetSymbolAddress((void**)&h2hi, g_h2hi); cudaGetSymbolAddress((void**)&h2lo, g_h2lo);
    cudaGetSymbolAddress((void**)&thi, g_thi);   cudaGetSymbolAddress((void**)&tlo, g_tlo);
    cudaGetSymbolAddress((void**)&winThi, g_winThi);   cudaGetSymbolAddress((void**)&winTlo, g_winTlo);
    cudaGetSymbolAddress((void**)&wqkvThi, g_wqkvThi); cudaGetSymbolAddress((void**)&wqkvTlo, g_wqkvTlo);
    cudaGetSymbolAddress((void**)&woutThi, g_woutThi); cudaGetSymbolAddress((void**)&woutTlo, g_woutTlo);
    cudaGetSymbolAddress((void**)&w1Thi, g_w1Thi);     cudaGetSymbolAddress((void**)&w1Tlo, g_w1Tlo);
    cudaGetSymbolAddress((void**)&w2Thi, g_w2Thi);     cudaGetSymbolAddress((void**)&w2Tlo, g_w2Tlo);

    cudaFuncSetAttribute(mma_gemm<false,false,false,true>, cudaFuncAttributeMaxDynamicSharedMemorySize, GEMM_SMEM);
    cudaFuncSetAttribute(mma_gemm<false,true, true, true>, cudaFuncAttributeMaxDynamicSharedMemorySize, GEMM_SMEM);
    cudaFuncSetAttribute(mma_gemm<true, false,true, false>,cudaFuncAttributeMaxDynamicSharedMemorySize, GEMM_SMEM);
    cudaFuncSetAttribute(mma_gemm<false,true, false,true>, cudaFuncAttributeMaxDynamicSharedMemorySize, GEMM_SMEM);

    // --- weight & input converts ---
    conv_hilo_kernel<<<(RR*DD/4 + 255)/256, 256>>>((const float4*)x, (__nv_bfloat162*)xhi, (__nv_bfloat162*)xlo, RR*DD/4);
    convT_kernel<<<dim3(DD/32,  DD/32), dim3(32,8)>>>(Win,  winThi,  winTlo,  DD, DD);
    convT_kernel<<<dim3(QKVW/32,DD/32), dim3(32,8)>>>(Wqkv, wqkvThi, wqkvTlo, DD, QKVW);
    convT_kernel<<<dim3(DD/32,  DD/32), dim3(32,8)>>>(Wout, woutThi, woutTlo, DD, DD);
    convT_kernel<<<dim3(DD/32,  DD/32), dim3(32,8)>>>(W1,   w1Thi,   w1Tlo,   DD, DD);
    convT_kernel<<<dim3(DD/32,  DD/32), dim3(32,8)>>>(W2,   w2Thi,   w2Tlo,   DD, DD);

    const dim3 gD(DD/128, RR/128);       // 8 x 32
    const dim3 gQ(QKVW/128, RR/128);     // 24 x 32

    // 1) t = x @ Win + bin
    mma_gemm<false,false,false,true><<<gD, 256, GEMM_SMEM>>>(xhi, xlo, winThi, winTlo, bin, nullptr,
                                                             t, nullptr, nullptr, RR, DD, DD);
    // 2) h = l2norm_scale(t) (+ emit hi/lo)
    l2norm_kernel<true><<<RR, 256>>>(t, attn_w, h, hhi, hlo);
    // 3) qkv = h @ Wqkv + bqkv
    mma_gemm<false,false,false,true><<<gQ, 256, GEMM_SMEM>>>(hhi, hlo, wqkvThi, wqkvTlo, bqkv, nullptr,
                                                             qkv, nullptr, nullptr, RR, QKVW, DD);
    // 4) RoPE
    rope_table_kernel<<<(SS*16 + 255)/256, 256>>>(cs, sn);
    rope_apply_kernel<<<(RR*NH*16 + 255)/256, 256>>>(qkv, cs, sn);
    // 5) attention (+ emit hi/lo)
    dim3 ga(SS/64, BB*NH);
    attn_kernel<<<ga, 256>>>(qkv, mask, ao, aohi, aolo);
    // 6) h2 = h + (ao @ Wout + bout) (+ emit)
    mma_gemm<false,true,true,true><<<gD, 256, GEMM_SMEM>>>(aohi, aolo, woutThi, woutTlo, bout, h,
                                                           h2, h2hi, h2lo, RR, DD, DD);
    // 7) t = silu(h2 @ W1 + b1) (emit only)
    mma_gemm<true,false,true,false><<<gD, 256, GEMM_SMEM>>>(h2hi, h2lo, w1Thi, w1Tlo, b1, nullptr,
                                                            nullptr, thi, tlo, RR, DD, DD);
    // 8) h = h2 + (t @ W2 + b2)
    mma_gemm<false,true,false,true><<<gD, 256, GEMM_SMEM>>>(thi, tlo, w2Thi, w2Tlo, b2, h2,
                                                            h, nullptr, nullptr, RR, DD, DD);
    // 9) out = l2norm_scale(h, ffn_norm_w)
    l2norm_kernel<false><<<RR, 256>>>(h, ffn_w, out, nullptr, nullptr);
}

// round 6
// speedup vs baseline: 2.1584x; 2.1584x over previous
#include <cuda_runtime.h>
#include <cuda_bf16.h>
#include <math.h>
#include <stdint.h>

// Problem constants
#define BB 2
#define SS 2048
#define DD 1024
#define NH 16
#define RR (BB*SS)          // 4096 rows
#define QKVW (3*DD)         // 3072
#define BH (BB*NH)          // 32

// ------------------------- scratch (static device memory) -------------------------
__device__ float g_h  [(size_t)RR*DD];
__device__ float g_h2 [(size_t)RR*DD];
__device__ float g_t  [(size_t)RR*DD];
__device__ float g_qkv[(size_t)RR*QKVW];
__device__ float g_cs [SS*16];
__device__ float g_sn [SS*16];
__device__ float g_vsum[BH*64];

#define BFA __device__ __align__(16) __nv_bfloat16
BFA g_xhi [(size_t)RR*DD];  BFA g_xlo [(size_t)RR*DD];
BFA g_hhi [(size_t)RR*DD];  BFA g_hlo [(size_t)RR*DD];
BFA g_aohi[(size_t)RR*DD];  BFA g_aolo[(size_t)RR*DD];
BFA g_h2hi[(size_t)RR*DD];  BFA g_h2lo[(size_t)RR*DD];
BFA g_thi [(size_t)RR*DD];  BFA g_tlo [(size_t)RR*DD];
BFA g_qb [(size_t)BH*SS*64];
BFA g_kb [(size_t)BH*SS*64];
BFA g_vb [(size_t)BH*SS*64];
BFA g_winThi [(size_t)DD*DD];    BFA g_winTlo [(size_t)DD*DD];
BFA g_wqkvThi[(size_t)QKVW*DD];  BFA g_wqkvTlo[(size_t)QKVW*DD];
BFA g_woutThi[(size_t)DD*DD];    BFA g_woutTlo[(size_t)DD*DD];
BFA g_w1Thi  [(size_t)DD*DD];    BFA g_w1Tlo  [(size_t)DD*DD];
BFA g_w2Thi  [(size_t)DD*DD];    BFA g_w2Tlo  [(size_t)DD*DD];

// ------------------------- base-ISA helpers (sm_103 base target) ------------------
__device__ __forceinline__ uint32_t smem_u32(const void* p) {
    uint32_t a;
    asm("{ .reg .u64 t; cvta.to.shared.u64 t, %1; cvt.u32.u64 %0, t; }" : "=r"(a) : "l"(p));
    return a;
}
__device__ __forceinline__ uint32_t swz(uint32_t off) { return off ^ ((off >> 3) & 0x70); }

#define CP16(dst, src) \
    asm volatile("cp.async.cg.shared.global [%0], [%1], 16;" :: "r"(dst), "l"(src))
#define CP_COMMIT() asm volatile("cp.async.commit_group;" ::: "memory")
#define CP_WAIT(n)  asm volatile("cp.async.wait_group %0;" :: "n"(n) : "memory")

__device__ __forceinline__ void ldsm4(uint32_t* r, uint32_t addr) {
    asm volatile("ldmatrix.sync.aligned.m8n8.x4.shared.b16 {%0,%1,%2,%3}, [%4];"
        : "=r"(r[0]), "=r"(r[1]), "=r"(r[2]), "=r"(r[3]) : "r"(addr));
}
__device__ __forceinline__ void ldsm4t(uint32_t* r, uint32_t addr) {
    asm volatile("ldmatrix.sync.aligned.m8n8.x4.trans.shared.b16 {%0,%1,%2,%3}, [%4];"
        : "=r"(r[0]), "=r"(r[1]), "=r"(r[2]), "=r"(r[3]) : "r"(addr));
}
__device__ __forceinline__ void mma_bf16(float* c, const uint32_t* a, const uint32_t* b) {
    asm volatile("mma.sync.aligned.m16n8k16.row.col.f32.bf16.bf16.f32 "
        "{%0,%1,%2,%3}, {%4,%5,%6,%7}, {%8,%9}, {%0,%1,%2,%3};"
        : "+f"(c[0]), "+f"(c[1]), "+f"(c[2]), "+f"(c[3])
        : "r"(a[0]), "r"(a[1]), "r"(a[2]), "r"(a[3]), "r"(b[0]), "r"(b[1]));
}
__device__ __forceinline__ uint32_t packbf(float a, float b) {
    __nv_bfloat162 t = __floats2bfloat162_rn(a, b);
    return *(uint32_t*)&t;
}
__device__ __forceinline__ void split2(float v, __nv_bfloat16& hi, __nv_bfloat16& lo) {
    hi = __float2bfloat16(v);
    lo = __float2bfloat16(v - __bfloat162float(hi));
}

// ------------------------- converts ------------------------------------------------
__global__ void conv_hilo_kernel(const float4* __restrict__ in,
                                 __nv_bfloat162* __restrict__ hi,
                                 __nv_bfloat162* __restrict__ lo, int n4)
{
    int i = blockIdx.x * blockDim.x + threadIdx.x;
    if (i >= n4) return;
    float4 v = in[i];
    __nv_bfloat16 h0, l0, h1, l1, h2, l2, h3, l3;
    split2(v.x, h0, l0); split2(v.y, h1, l1); split2(v.z, h2, l2); split2(v.w, h3, l3);
    hi[2*i]   = __nv_bfloat162(h0, h1);  hi[2*i+1] = __nv_bfloat162(h2, h3);
    lo[2*i]   = __nv_bfloat162(l0, l1);  lo[2*i+1] = __nv_bfloat162(l2, l3);
}

__global__ void convT_kernel(const float* __restrict__ W,
                             __nv_bfloat16* __restrict__ Thi, __nv_bfloat16* __restrict__ Tlo,
                             int K, int N)
{
    __shared__ float tile[32][33];
    const int n0 = blockIdx.x * 32, k0 = blockIdx.y * 32;
    const int tx = threadIdx.x, ty = threadIdx.y;
    #pragma unroll
    for (int j = 0; j < 32; j += 8)
        tile[ty + j][tx] = W[(size_t)(k0 + ty + j) * N + n0 + tx];
    __syncthreads();
    #pragma unroll
    for (int j = 0; j < 32; j += 8) {
        float v = tile[tx][ty + j];
        __nv_bfloat16 hb, lb; split2(v, hb, lb);
        size_t o = (size_t)(n0 + ty + j) * K + k0 + tx;
        Thi[o] = hb; Tlo[o] = lb;
    }
}

// ------------------------- mma.sync dense GEMM (3-pass bf16 split) -----------------
#define GBK 64
#define STAGE_BYTES 65536
#define GEMM_SMEM (1024 + 2*STAGE_BYTES)

__device__ __forceinline__ void issue_stage(uint32_t st32,
    const __nv_bfloat16* __restrict__ Ahi, const __nv_bfloat16* __restrict__ Alo,
    const __nv_bfloat16* __restrict__ Bhi, const __nv_bfloat16* __restrict__ Blo,
    int m0, int n0, int k0, int K, int tid)
{
    #pragma unroll
    for (int it = 0; it < 16; it++) {
        int u = tid + it * 256;
        int mat = u >> 10;
        int w = u & 1023;
        int row = w >> 3;
        int c16 = w & 7;
        const __nv_bfloat16* src;
        int grow;
        if (mat == 0)      { src = Ahi; grow = m0 + row; }
        else if (mat == 1) { src = Alo; grow = m0 + row; }
        else if (mat == 2) { src = Bhi; grow = n0 + row; }
        else               { src = Blo; grow = n0 + row; }
        uint32_t off = swz((uint32_t)(row * 128 + c16 * 16));
        CP16(st32 + (mat << 14) + off,
             (const void*)(src + (size_t)grow * K + k0 + c16 * 8));
    }
}

template<bool SILU, bool RESID, bool EMIT, bool WF32>
__global__ __launch_bounds__(256)
void mma_gemm(const __nv_bfloat16* __restrict__ Ahi, const __nv_bfloat16* __restrict__ Alo,
              const __nv_bfloat16* __restrict__ Bhi, const __nv_bfloat16* __restrict__ Blo,
              const float* __restrict__ bias, const float* __restrict__ resid,
              float* __restrict__ C, __nv_bfloat16* __restrict__ Chi, __nv_bfloat16* __restrict__ Clo,
              int M, int N, int K)
{
    extern __shared__ char smem_raw[];
    const uint32_t raw32 = smem_u32(smem_raw);
    const uint32_t base32 = (raw32 + 1023u) & ~1023u;

    const int tid = threadIdx.x;
    const int lane = tid & 31;
    const int wid = tid >> 5;
    const int wm = wid & 3;
    const int wn = wid >> 2;
    const int m0 = blockIdx.y * 128;
    const int n0 = blockIdx.x * 128;

    float acc[2][8][4];
    #pragma unroll
    for (int mt = 0; mt < 2; mt++)
        #pragma unroll
        for (int nt = 0; nt < 8; nt++)
            #pragma unroll
            for (int q = 0; q < 4; q++) acc[mt][nt][q] = 0.f;

    const int NK = K / GBK;
    issue_stage(base32, Ahi, Alo, Bhi, Blo, m0, n0, 0, K, tid);
    CP_COMMIT();

    const uint32_t aoff0 = (uint32_t)((wm * 32 + (lane & 15)) * 128 + ((lane >> 4) & 1) * 16);
    const uint32_t boff0 = (uint32_t)((wn * 64 + (lane & 7) + ((lane >> 4) & 1) * 8) * 128
                                      + ((lane >> 3) & 1) * 16);

    for (int i = 0; i < NK; i++) {
        const uint32_t cur32 = base32 + (uint32_t)(i & 1) * STAGE_BYTES;
        if (i + 1 < NK) {
            issue_stage(base32 + (uint32_t)((i + 1) & 1) * STAGE_BYTES,
                        Ahi, Alo, Bhi, Blo, m0, n0, (i + 1) * GBK, K, tid);
            CP_COMMIT();
            CP_WAIT(1);
        } else {
            CP_WAIT(0);
        }
        __syncthreads();

        #pragma unroll
        for (int ks = 0; ks < 4; ks++) {
            const uint32_t ka = aoff0 + ks * 32;
            const uint32_t kb = boff0 + ks * 32;
            uint32_t ah[2][4], al[2][4], bq[4][4];
            ldsm4(ah[0], cur32 + swz(ka));
            ldsm4(ah[1], cur32 + swz(ka + 16 * 128));
            ldsm4(al[0], cur32 + 16384 + swz(ka));
            ldsm4(al[1], cur32 + 16384 + swz(ka + 16 * 128));
            #pragma unroll
            for (int g = 0; g < 4; g++)
                ldsm4(bq[g], cur32 + 32768 + swz(kb + g * 16 * 128));

            #pragma unroll
            for (int mt = 0; mt < 2; mt++)
                #pragma unroll
                for (int nt = 0; nt < 8; nt++)
                    mma_bf16(acc[mt][nt], ah[mt], &bq[nt >> 1][(nt & 1) * 2]);
            #pragma unroll
            for (int mt = 0; mt < 2; mt++)
                #pragma unroll
                for (int nt = 0; nt < 8; nt++)
                    mma_bf16(acc[mt][nt], al[mt], &bq[nt >> 1][(nt & 1) * 2]);
            #pragma unroll
            for (int g = 0; g < 4; g++)
                ldsm4(bq[g], cur32 + 49152 + swz(kb + g * 16 * 128));
            #pragma unroll
            for (int mt = 0; mt < 2; mt++)
                #pragma unroll
                for (int nt = 0; nt < 8; nt++)
                    mma_bf16(acc[mt][nt], ah[mt], &bq[nt >> 1][(nt & 1) * 2]);
        }
        __syncthreads();
    }

    #pragma unroll
    for (int mt = 0; mt < 2; mt++) {
        #pragma unroll
        for (int half = 0; half < 2; half++) {
            const int row = m0 + wm * 32 + mt * 16 + (lane >> 2) + half * 8;
            #pragma unroll
            for (int nt = 0; nt < 8; nt++) {
                const int col = n0 + wn * 64 + nt * 8 + (lane & 3) * 2;
                float v0 = acc[mt][nt][half * 2]     + bias[col];
                float v1 = acc[mt][nt][half * 2 + 1] + bias[col + 1];
                const size_t o = (size_t)row * N + col;
                if (RESID) { v0 += resid[o]; v1 += resid[o + 1]; }
                if (SILU)  { v0 = v0 / (1.f + expf(-v0)); v1 = v1 / (1.f + expf(-v1)); }
                if (WF32)  { *(float2*)(C + o) = make_float2(v0, v1); }
                if (EMIT) {
                    __nv_bfloat16 h0, l0, h1, l1;
                    split2(v0, h0, l0); split2(v1, h1, l1);
                    *(__nv_bfloat162*)(Chi + o) = __nv_bfloat162(h0, h1);
                    *(__nv_bfloat162*)(Clo + o) = __nv_bfloat162(l0, l1);
                }
            }
        }
    }
}

// ------------------------- row L2-norm scale (+optional hi/lo emit) ---------------
template<bool EMIT>
__global__ __launch_bounds__(256)
void l2norm_kernel(const float* __restrict__ x, const float* __restrict__ w,
                   float* __restrict__ out,
                   __nv_bfloat16* __restrict__ ohi, __nv_bfloat16* __restrict__ olo)
{
    const int row = blockIdx.x;
    const int tid = threadIdx.x;
    const float* xr = x + (size_t)row * DD;

    float4 v = *(const float4*)(xr + tid * 4);
    float ss = v.x*v.x + v.y*v.y + v.z*v.z + v.w*v.w;

    __shared__ float red[8];
    __shared__ float inv_s;
    #pragma unroll
    for (int o = 16; o > 0; o >>= 1) ss += __shfl_xor_sync(0xffffffffu, ss, o);
    if ((tid & 31) == 0) red[tid >> 5] = ss;
    __syncthreads();
    if (tid < 32) {
        float t = (tid < 8) ? red[tid] : 0.f;
        #pragma unroll
        for (int o = 4; o > 0; o >>= 1) t += __shfl_xor_sync(0xffffffffu, t, o);
        if (tid == 0) inv_s = 1.f / (sqrtf(t) + 1e-8f);
    }
    __syncthreads();

    const float inv = inv_s;
    float4 wv = *(const float4*)(w + tid * 4);
    float4 o4 = make_float4(wv.x*v.x*inv, wv.y*v.y*inv, wv.z*v.z*inv, wv.w*v.w*inv);
    *(float4*)(out + (size_t)row * DD + tid * 4) = o4;
    if (EMIT) {
        __nv_bfloat16 h0,l0,h1,l1,h2,l2,h3,l3;
        split2(o4.x,h0,l0); split2(o4.y,h1,l1); split2(o4.z,h2,l2); split2(o4.w,h3,l3);
        size_t ob = (size_t)row * DD + tid * 4;
        *(__nv_bfloat162*)(ohi + ob)     = __nv_bfloat162(h0, h1);
        *(__nv_bfloat162*)(ohi + ob + 2) = __nv_bfloat162(h2, h3);
        *(__nv_bfloat162*)(olo + ob)     = __nv_bfloat162(l0, l1);
        *(__nv_bfloat162*)(olo + ob + 2) = __nv_bfloat162(l2, l3);
    }
}

// ------------------------- RoPE ----------------------------------------------------
__global__ void rope_table_kernel(float* __restrict__ cs, float* __restrict__ sn)
{
    int idx = blockIdx.x * blockDim.x + threadIdx.x;
    if (idx >= SS * 16) return;
    int i = idx & 15, pos = idx >> 4;
    double inv = 1.0 / pow(10000.0, (double)(2*i) / 32.0);
    double ang = (double)pos * inv;
    cs[idx] = (float)cos(ang);
    sn[idx] = (float)sin(ang);
}

// qkv fp32 -> head-major bf16 Q,K (roped) + V
__global__ void rope_bf16_kernel(const float* __restrict__ qkv,
                                 const float* __restrict__ cs, const float* __restrict__ sn,
                                 __nv_bfloat16* __restrict__ qb, __nv_bfloat16* __restrict__ kb,
                                 __nv_bfloat16* __restrict__ vb)
{
    int idx = blockIdx.x * blockDim.x + threadIdx.x;
    if (idx >= BH * SS * 32) return;
    const int d2 = idx & 31;
    const int s  = (idx >> 5) & (SS - 1);
    const int bh = idx >> 16;
    const int b = bh >> 4, h = bh & 15;

    const float* base = qkv + ((size_t)(b*SS + s)) * QKVW + h*192 + 2*d2;
    float2 q = *(const float2*)(base);
    float2 k = *(const float2*)(base + 64);
    float2 v = *(const float2*)(base + 128);
    if (d2 < 16) {
        const float c = cs[s*16 + d2], sv = sn[s*16 + d2];
        q = make_float2(q.x*c - q.y*sv, q.y*c + q.x*sv);
        k = make_float2(k.x*c - k.y*sv, k.y*c + k.x*sv);
    }
    const size_t o = ((size_t)bh*SS + s)*64 + 2*d2;
    *(__nv_bfloat162*)(qb + o) = __floats2bfloat162_rn(q.x, q.y);
    *(__nv_bfloat162*)(kb + o) = __floats2bfloat162_rn(k.x, k.y);
    *(__nv_bfloat162*)(vb + o) = __floats2bfloat162_rn(v.x, v.y);
}

// exact fp32 V column sums per (b,h)
__global__ void vsum_kernel(const float* __restrict__ qkv, float* __restrict__ vsum)
{
    __shared__ float red[4][64];
    const int bh = blockIdx.x;
    const int b = bh >> 4, h = bh & 15;
    const int d = threadIdx.x & 63, p = threadIdx.x >> 6;
    float s = 0.f;
    for (int t = p; t < SS; t += 4)
        s += qkv[((size_t)(b*SS + t)) * QKVW + h*192 + 128 + d];
    red[p][d] = s;
    __syncthreads();
    if (p == 0) vsum[bh*64 + d] = red[0][d] + red[1][d] + red[2][d] + red[3][d];
}

// ------------------------- tensor-core attention (linear log-softmax) -------------
// per CTA: 128 q-rows of one (b,h); 8 warps x 16 rows; 64-key chunks, double buffer.
#define ATT_SMEM (1024 + 48*1024)

__device__ __forceinline__ void issue_kv(uint32_t st,
    const __nv_bfloat16* __restrict__ kbase, const __nv_bfloat16* __restrict__ vbase,
    int t0, int tid)
{
    #pragma unroll
    for (int it = 0; it < 2; it++) {
        int idx = tid + it * 256;            // 0..511
        int row = idx >> 3, c16 = idx & 7;
        uint32_t soff = swz((uint32_t)(row * 128 + c16 * 16));
        CP16(st + soff,        (const void*)(kbase + (size_t)(t0 + row) * 64 + c16 * 8));
        CP16(st + 8192 + soff, (const void*)(vbase + (size_t)(t0 + row) * 64 + c16 * 8));
    }
}

__global__ __launch_bounds__(256)
void attn_mma_kernel(const __nv_bfloat16* __restrict__ qb,
                     const __nv_bfloat16* __restrict__ kb,
                     const __nv_bfloat16* __restrict__ vb,
                     const float* __restrict__ mask,
                     const float* __restrict__ vsum,
                     __nv_bfloat16* __restrict__ aohi,
                     __nv_bfloat16* __restrict__ aolo)
{
    extern __shared__ char sm_raw[];
    const uint32_t raw32 = smem_u32(sm_raw);
    const uint32_t s32 = (raw32 + 1023u) & ~1023u;  // Q at s32, stages at +16K

    const int bh = blockIdx.y;
    const int b = bh >> 4, h = bh & 15;
    const int s0 = blockIdx.x * 128;
    const int tid = threadIdx.x, lane = tid & 31, wid = tid >> 5;

    const __nv_bfloat16* qbase = qb + ((size_t)bh*SS + s0) * 64;
    const __nv_bfloat16* kbase = kb + (size_t)bh*SS*64;
    const __nv_bfloat16* vbase = vb + (size_t)bh*SS*64;

    // Q block 128x64 bf16 -> smem (group 0)
    #pragma unroll
    for (int it = 0; it < 4; it++) {
        int idx = tid + it * 256;            // 0..1023
        int row = idx >> 3, c16 = idx & 7;
        CP16(s32 + swz((uint32_t)(row * 128 + c16 * 16)),
             (const void*)(qbase + (size_t)row * 64 + c16 * 8));
    }
    CP_COMMIT();
    issue_kv(s32 + 16384, kbase, vbase, 0, tid);   // chunk 0 (group 1)
    CP_COMMIT();

    CP_WAIT(1);                                     // Q ready
    __syncthreads();

    // Q fragments: warp owns rows wid*16..+15
    uint32_t qf[4][4];
    #pragma unroll
    for (int ks = 0; ks < 4; ks++)
        ldsm4(qf[ks], s32 + swz((uint32_t)((wid*16 + (lane & 15)) * 128 + ks*32 + (lane >> 4) * 16)));

    float oacc[8][4];
    #pragma unroll
    for (int j = 0; j < 8; j++)
        #pragma unroll
        for (int q = 0; q < 4; q++) oacc[j][q] = 0.f;
    float m0 = -INFINITY, m1 = -INFINITY, l0 = 0.f, l1 = 0.f;

    const float scale = 0.125f;
    const int r = lane >> 2;
    const float* mrow0 = mask + (size_t)b*SS*SS + (size_t)(s0 + wid*16 + r) * SS + (lane & 3) * 2;

    for (int i = 0; i < 32; i++) {
        const uint32_t cur = s32 + 16384 + (uint32_t)(i & 1) * 16384;
        if (i + 1 < 32) {
            issue_kv(s32 + 16384 + (uint32_t)((i + 1) & 1) * 16384, kbase, vbase, (i + 1) * 64, tid);
            CP_COMMIT();
            CP_WAIT(1);
        } else {
            CP_WAIT(0);
        }
        __syncthreads();

        // ---- S = Q @ K^T ----
        float sacc[8][4];
        #pragma unroll
        for (int j = 0; j < 8; j++)
            #pragma unroll
            for (int q = 0; q < 4; q++) sacc[j][q] = 0.f;

        #pragma unroll
        for (int ks = 0; ks < 4; ks++) {
            #pragma unroll
            for (int j = 0; j < 4; j++) {
                uint32_t kf[4];
                ldsm4(kf, cur + swz((uint32_t)((j*16 + (lane >> 4) * 8 + (lane & 7)) * 128
                                               + ks*32 + ((lane >> 3) & 1) * 16)));
                mma_bf16(sacc[2*j],     qf[ks], &kf[0]);
                mma_bf16(sacc[2*j + 1], qf[ks], &kf[2]);
            }
        }

        // ---- scale + mask ----
        const float* mr = mrow0 + i * 64;
        #pragma unroll
        for (int j = 0; j < 8; j++) {
            float2 mk0 = *(const float2*)(mr + j*8);
            float2 mk1 = *(const float2*)(mr + 8*SS + j*8);
            sacc[j][0] = sacc[j][0]*scale + mk0.x;
            sacc[j][1] = sacc[j][1]*scale + mk0.y;
            sacc[j][2] = sacc[j][2]*scale + mk1.x;
            sacc[j][3] = sacc[j][3]*scale + mk1.y;
        }

        // ---- running logsumexp stats (rows r, r+8 within warp) ----
        float tm0 = -INFINITY, tm1 = -INFINITY;
        #pragma unroll
        for (int j = 0; j < 8; j++) {
            tm0 = fmaxf(tm0, fmaxf(sacc[j][0], sacc[j][1]));
            tm1 = fmaxf(tm1, fmaxf(sacc[j][2], sacc[j][3]));
        }
        tm0 = fmaxf(tm0, __shfl_xor_sync(0xffffffffu, tm0, 1));
        tm0 = fmaxf(tm0, __shfl_xor_sync(0xffffffffu, tm0, 2));
        tm1 = fmaxf(tm1, __shfl_xor_sync(0xffffffffu, tm1, 1));
        tm1 = fmaxf(tm1, __shfl_xor_sync(0xffffffffu, tm1, 2));
        const float nm0 = fmaxf(m0, tm0), nm1 = fmaxf(m1, tm1);
        float e0 = 0.f, e1 = 0.f;
        #pragma unroll
        for (int j = 0; j < 8; j++) {
            e0 += __expf(sacc[j][0] - nm0) + __expf(sacc[j][1] - nm0);
            e1 += __expf(sacc[j][2] - nm1) + __expf(sacc[j][3] - nm1);
        }
        e0 += __shfl_xor_sync(0xffffffffu, e0, 1);
        e0 += __shfl_xor_sync(0xffffffffu, e0, 2);
        e1 += __shfl_xor_sync(0xffffffffu, e1, 1);
        e1 += __shfl_xor_sync(0xffffffffu, e1, 2);
        l0 = l0 * __expf(m0 - nm0) + e0;  m0 = nm0;
        l1 = l1 * __expf(m1 - nm1) + e1;  m1 = nm1;

        // ---- S (bf16) @ V: C-frag -> A-frag repack ----
        uint32_t sf[4][4];
        #pragma unroll
        for (int ks = 0; ks < 4; ks++) {
            sf[ks][0] = packbf(sacc[2*ks][0],     sacc[2*ks][1]);
            sf[ks][1] = packbf(sacc[2*ks][2],     sacc[2*ks][3]);
            sf[ks][2] = packbf(sacc[2*ks + 1][0], sacc[2*ks + 1][1]);
            sf[ks][3] = packbf(sacc[2*ks + 1][2], sacc[2*ks + 1][3]);
        }
        const uint32_t vst = cur + 8192;
        #pragma unroll
        for (int ks = 0; ks < 4; ks++) {
            #pragma unroll
            for (int db = 0; db < 4; db++) {
                uint32_t vf[4];
                ldsm4t(vf, vst + swz((uint32_t)((ks*16 + ((lane >> 3) & 1) * 8 + (lane & 7)) * 128
                                                + db*32 + (lane >> 4) * 16)));
                mma_bf16(oacc[2*db],     sf[ks], &vf[0]);
                mma_bf16(oacc[2*db + 1], sf[ks], &vf[2]);
            }
        }
        __syncthreads();
    }

    // ---- epilogue: ao = oacc - lse * vsum ----
    const float lse0 = m0 + logf(l0);
    const float lse1 = m1 + logf(l1);
    const size_t row0 = (size_t)(b*SS + s0 + wid*16 + r);
    #pragma unroll
    for (int j = 0; j < 8; j++) {
        const int dcol = j*8 + (lane & 3) * 2;
        float2 vs = *(const float2*)(vsum + bh*64 + dcol);
        const size_t o0 = row0 * DD + h*64 + dcol;
        const size_t o1 = o0 + 8 * DD;
        float a00 = oacc[j][0] - lse0 * vs.x;
        float a01 = oacc[j][1] - lse0 * vs.y;
        float a10 = oacc[j][2] - lse1 * vs.x;
        float a11 = oacc[j][3] - lse1 * vs.y;
        __nv_bfloat16 h0,l0b,h1,l1b;
        split2(a00, h0, l0b); split2(a01, h1, l1b);
        *(__nv_bfloat162*)(aohi + o0) = __nv_bfloat162(h0, h1);
        *(__nv_bfloat162*)(aolo + o0) = __nv_bfloat162(l0b, l1b);
        split2(a10, h0, l0b); split2(a11, h1, l1b);
        *(__nv_bfloat162*)(aohi + o1) = __nv_bfloat162(h0, h1);
        *(__nv_bfloat162*)(aolo + o1) = __nv_bfloat162(l0b, l1b);
    }
}

// ------------------------- launch -------------------------------------------------
extern "C" void kernel_launch(void* const* d_in, const int* in_sizes, int n_in,
                              void* d_out, int out_size)
{
    const float* x      = (const float*)d_in[0];
    const float* mask   = (const float*)d_in[1];
    const float* Win    = (const float*)d_in[2];
    const float* bin    = (const float*)d_in[3];
    const float* attn_w = (const float*)d_in[4];
    const float* Wqkv   = (const float*)d_in[5];
    const float* bqkv   = (const float*)d_in[6];
    const float* Wout   = (const float*)d_in[7];
    const float* bout   = (const float*)d_in[8];
    const float* W1     = (const float*)d_in[9];
    const float* b1     = (const float*)d_in[10];
    const float* W2     = (const float*)d_in[11];
    const float* b2     = (const float*)d_in[12];
    const float* ffn_w  = (const float*)d_in[13];
    float* out = (float*)d_out;

    float *h, *h2, *t, *qkv, *cs, *sn, *vsum;
    cudaGetSymbolAddress((void**)&h,    g_h);
    cudaGetSymbolAddress((void**)&h2,   g_h2);
    cudaGetSymbolAddress((void**)&t,    g_t);
    cudaGetSymbolAddress((void**)&qkv,  g_qkv);
    cudaGetSymbolAddress((void**)&cs,   g_cs);
    cudaGetSymbolAddress((void**)&sn,   g_sn);
    cudaGetSymbolAddress((void**)&vsum, g_vsum);

    __nv_bfloat16 *xhi,*xlo,*hhi,*hlo,*aohi,*aolo,*h2hi,*h2lo,*thi,*tlo,*qb,*kb,*vb;
    __nv_bfloat16 *winThi,*winTlo,*wqkvThi,*wqkvTlo,*woutThi,*woutTlo,*w1Thi,*w1Tlo,*w2Thi,*w2Tlo;
    cudaGetSymbolAddress((void**)&xhi, g_xhi);   cudaGetSymbolAddress((void**)&xlo, g_xlo);
    cudaGetSymbolAddress((void**)&hhi, g_hhi);   cudaGetSymbolAddress((void**)&hlo, g_hlo);
    cudaGetSymbolAddress((void**)&aohi, g_aohi); cudaGetSymbolAddress((void**)&aolo, g_aolo);
    cudaGetSymbolAddress((void**)&h2hi, g_h2hi); cudaGetSymbolAddress((void**)&h2lo, g_h2lo);
    cudaGetSymbolAddress((void**)&thi, g_thi);   cudaGetSymbolAddress((void**)&tlo, g_tlo);
    cudaGetSymbolAddress((void**)&qb, g_qb);
    cudaGetSymbolAddress((void**)&kb, g_kb);
    cudaGetSymbolAddress((void**)&vb, g_vb);
    cudaGetSymbolAddress((void**)&winThi, g_winThi);   cudaGetSymbolAddress((void**)&winTlo, g_winTlo);
    cudaGetSymbolAddress((void**)&wqkvThi, g_wqkvThi); cudaGetSymbolAddress((void**)&wqkvTlo, g_wqkvTlo);
    cudaGetSymbolAddress((void**)&woutThi, g_woutThi); cudaGetSymbolAddress((void**)&woutTlo, g_woutTlo);
    cudaGetSymbolAddress((void**)&w1Thi, g_w1Thi);     cudaGetSymbolAddress((void**)&w1Tlo, g_w1Tlo);
    cudaGetSymbolAddress((void**)&w2Thi, g_w2Thi);     cudaGetSymbolAddress((void**)&w2Tlo, g_w2Tlo);

    cudaFuncSetAttribute(mma_gemm<false,false,false,true>, cudaFuncAttributeMaxDynamicSharedMemorySize, GEMM_SMEM);
    cudaFuncSetAttribute(mma_gemm<false,true, true, true>, cudaFuncAttributeMaxDynamicSharedMemorySize, GEMM_SMEM);
    cudaFuncSetAttribute(mma_gemm<true, false,true, false>,cudaFuncAttributeMaxDynamicSharedMemorySize, GEMM_SMEM);
    cudaFuncSetAttribute(mma_gemm<false,true, false,true>, cudaFuncAttributeMaxDynamicSharedMemorySize, GEMM_SMEM);
    cudaFuncSetAttribute(attn_mma_kernel, cudaFuncAttributeMaxDynamicSharedMemorySize, ATT_SMEM);

    // --- weight & input converts ---
    conv_hilo_kernel<<<(RR*DD/4 + 255)/256, 256>>>((const float4*)x, (__nv_bfloat162*)xhi, (__nv_bfloat162*)xlo, RR*DD/4);
    convT_kernel<<<dim3(DD/32,  DD/32), dim3(32,8)>>>(Win,  winThi,  winTlo,  DD, DD);
    convT_kernel<<<dim3(QKVW/32,DD/32), dim3(32,8)>>>(Wqkv, wqkvThi, wqkvTlo, DD, QKVW);
    convT_kernel<<<dim3(DD/32,  DD/32), dim3(32,8)>>>(Wout, woutThi, woutTlo, DD, DD);
    convT_kernel<<<dim3(DD/32,  DD/32), dim3(32,8)>>>(W1,   w1Thi,   w1Tlo,   DD, DD);
    convT_kernel<<<dim3(DD/32,  DD/32), dim3(32,8)>>>(W2,   w2Thi,   w2Tlo,   DD, DD);
    rope_table_kernel<<<(SS*16 + 255)/256, 256>>>(cs, sn);

    const dim3 gD(DD/128, RR/128);
    const dim3 gQ(QKVW/128, RR/128);

    // 1) t = x @ Win + bin
    mma_gemm<false,false,false,true><<<gD, 256, GEMM_SMEM>>>(xhi, xlo, winThi, winTlo, bin, nullptr,
                                                             t, nullptr, nullptr, RR, DD, DD);
    // 2) h = l2norm_scale(t) (+ emit hi/lo)
    l2norm_kernel<true><<<RR, 256>>>(t, attn_w, h, hhi, hlo);
    // 3) qkv = h @ Wqkv + bqkv
    mma_gemm<false,false,false,true><<<gQ, 256, GEMM_SMEM>>>(hhi, hlo, wqkvThi, wqkvTlo, bqkv, nullptr,
                                                             qkv, nullptr, nullptr, RR, QKVW, DD);
    // 4) RoPE + bf16 repack + exact vsum
    rope_bf16_kernel<<<(BH*SS*32 + 255)/256, 256>>>(qkv, cs, sn, qb, kb, vb);
    vsum_kernel<<<BH, 256>>>(qkv, vsum);
    // 5) tensor-core attention -> aohi/aolo
    attn_mma_kernel<<<dim3(SS/128, BH), 256, ATT_SMEM>>>(qb, kb, vb, mask, vsum, aohi, aolo);
    // 6) h2 = h + (ao @ Wout + bout) (+ emit)
    mma_gemm<false,true,true,true><<<gD, 256, GEMM_SMEM>>>(aohi, aolo, woutThi, woutTlo, bout, h,
                                                           h2, h2hi, h2lo, RR, DD, DD);
    // 7) t = silu(h2 @ W1 + b1) (emit only)
    mma_gemm<true,false,true,false><<<gD, 256, GEMM_SMEM>>>(h2hi, h2lo, w1Thi, w1Tlo, b1, nullptr,
                                                            nullptr, thi, tlo, RR, DD, DD);
    // 8) h = h2 + (t @ W2 + b2)
    mma_gemm<false,true,false,true><<<gD, 256, GEMM_SMEM>>>(thi, tlo, w2Thi, w2Tlo, b2, h2,
                                                            h, nullptr, nullptr, RR, DD, DD);
    // 9) out = l2norm_scale(h, ffn_norm_w)
    l2norm_kernel<false><<<RR, 256>>>(h, ffn_w, out, nullptr, nullptr);
}

// round 7
// speedup vs baseline: 2.1652x; 1.0031x over previous
#include <cuda_runtime.h>
#include <cuda_bf16.h>
#include <math.h>
#include <stdint.h>

// Problem constants
#define BB 2
#define SS 2048
#define DD 1024
#define NH 16
#define RR (BB*SS)          // 4096 rows
#define QKVW (3*DD)         // 3072
#define BH (BB*NH)          // 32

// ------------------------- scratch (static device memory) -------------------------
__device__ float g_h  [(size_t)RR*DD];
__device__ float g_h2 [(size_t)RR*DD];
__device__ float g_t  [(size_t)RR*DD];
__device__ float g_qkv[(size_t)RR*QKVW];
__device__ float g_cs [SS*16];
__device__ float g_sn [SS*16];
__device__ float g_vsum[BH*64];

#define BFA __device__ __align__(16) __nv_bfloat16
BFA g_xhi [(size_t)RR*DD];  BFA g_xlo [(size_t)RR*DD];
BFA g_hhi [(size_t)RR*DD];  BFA g_hlo [(size_t)RR*DD];
BFA g_aohi[(size_t)RR*DD];  BFA g_aolo[(size_t)RR*DD];
BFA g_h2hi[(size_t)RR*DD];  BFA g_h2lo[(size_t)RR*DD];
BFA g_thi [(size_t)RR*DD];  BFA g_tlo [(size_t)RR*DD];
BFA g_qb [(size_t)BH*SS*64];
BFA g_kb [(size_t)BH*SS*64];
BFA g_vb [(size_t)BH*SS*64];
BFA g_winThi [(size_t)DD*DD];    BFA g_winTlo [(size_t)DD*DD];
BFA g_wqkvThi[(size_t)QKVW*DD];  BFA g_wqkvTlo[(size_t)QKVW*DD];
BFA g_woutThi[(size_t)DD*DD];    BFA g_woutTlo[(size_t)DD*DD];
BFA g_w1Thi  [(size_t)DD*DD];    BFA g_w1Tlo  [(size_t)DD*DD];
BFA g_w2Thi  [(size_t)DD*DD];    BFA g_w2Tlo  [(size_t)DD*DD];

// ------------------------- base-ISA helpers (sm_103 base target) ------------------
__device__ __forceinline__ uint32_t smem_u32(const void* p) {
    uint32_t a;
    asm("{ .reg .u64 t; cvta.to.shared.u64 t, %1; cvt.u32.u64 %0, t; }" : "=r"(a) : "l"(p));
    return a;
}
__device__ __forceinline__ uint32_t swz(uint32_t off) { return off ^ ((off >> 3) & 0x70); }

#define CP16(dst, src) \
    asm volatile("cp.async.cg.shared.global [%0], [%1], 16;" :: "r"(dst), "l"(src))
#define CP_COMMIT() asm volatile("cp.async.commit_group;" ::: "memory")
#define CP_WAIT(n)  asm volatile("cp.async.wait_group %0;" :: "n"(n) : "memory")

__device__ __forceinline__ void ldsm4(uint32_t* r, uint32_t addr) {
    asm volatile("ldmatrix.sync.aligned.m8n8.x4.shared.b16 {%0,%1,%2,%3}, [%4];"
        : "=r"(r[0]), "=r"(r[1]), "=r"(r[2]), "=r"(r[3]) : "r"(addr));
}
__device__ __forceinline__ void ldsm4t(uint32_t* r, uint32_t addr) {
    asm volatile("ldmatrix.sync.aligned.m8n8.x4.trans.shared.b16 {%0,%1,%2,%3}, [%4];"
        : "=r"(r[0]), "=r"(r[1]), "=r"(r[2]), "=r"(r[3]) : "r"(addr));
}
__device__ __forceinline__ void mma_bf16(float* c, const uint32_t* a, const uint32_t* b) {
    asm volatile("mma.sync.aligned.m16n8k16.row.col.f32.bf16.bf16.f32 "
        "{%0,%1,%2,%3}, {%4,%5,%6,%7}, {%8,%9}, {%0,%1,%2,%3};"
        : "+f"(c[0]), "+f"(c[1]), "+f"(c[2]), "+f"(c[3])
        : "r"(a[0]), "r"(a[1]), "r"(a[2]), "r"(a[3]), "r"(b[0]), "r"(b[1]));
}
__device__ __forceinline__ uint32_t packbf(float a, float b) {
    __nv_bfloat162 t = __floats2bfloat162_rn(a, b);
    return *(uint32_t*)&t;
}
__device__ __forceinline__ void split2(float v, __nv_bfloat16& hi, __nv_bfloat16& lo) {
    hi = __float2bfloat16(v);
    lo = __float2bfloat16(v - __bfloat162float(hi));
}

// ------------------------- converts ------------------------------------------------
__global__ void conv_hilo_kernel(const float4* __restrict__ in,
                                 __nv_bfloat162* __restrict__ hi,
                                 __nv_bfloat162* __restrict__ lo, int n4)
{
    int i = blockIdx.x * blockDim.x + threadIdx.x;
    if (i >= n4) return;
    float4 v = in[i];
    __nv_bfloat16 h0, l0, h1, l1, h2, l2, h3, l3;
    split2(v.x, h0, l0); split2(v.y, h1, l1); split2(v.z, h2, l2); split2(v.w, h3, l3);
    hi[2*i]   = __nv_bfloat162(h0, h1);  hi[2*i+1] = __nv_bfloat162(h2, h3);
    lo[2*i]   = __nv_bfloat162(l0, l1);  lo[2*i+1] = __nv_bfloat162(l2, l3);
}

__global__ void convT_kernel(const float* __restrict__ W,
                             __nv_bfloat16* __restrict__ Thi, __nv_bfloat16* __restrict__ Tlo,
                             int K, int N)
{
    __shared__ float tile[32][33];
    const int n0 = blockIdx.x * 32, k0 = blockIdx.y * 32;
    const int tx = threadIdx.x, ty = threadIdx.y;
    #pragma unroll
    for (int j = 0; j < 32; j += 8)
        tile[ty + j][tx] = W[(size_t)(k0 + ty + j) * N + n0 + tx];
    __syncthreads();
    #pragma unroll
    for (int j = 0; j < 32; j += 8) {
        float v = tile[tx][ty + j];
        __nv_bfloat16 hb, lb; split2(v, hb, lb);
        size_t o = (size_t)(n0 + ty + j) * K + k0 + tx;
        Thi[o] = hb; Tlo[o] = lb;
    }
}

// ------------------------- mma.sync dense GEMM (3-pass bf16 split) -----------------
#define GBK 64
#define STAGE_BYTES 65536
#define GEMM_SMEM (1024 + 2*STAGE_BYTES)

__device__ __forceinline__ void issue_stage(uint32_t st32,
    const __nv_bfloat16* __restrict__ Ahi, const __nv_bfloat16* __restrict__ Alo,
    const __nv_bfloat16* __restrict__ Bhi, const __nv_bfloat16* __restrict__ Blo,
    int m0, int n0, int k0, int K, int tid)
{
    #pragma unroll
    for (int it = 0; it < 16; it++) {
        int u = tid + it * 256;
        int mat = u >> 10;
        int w = u & 1023;
        int row = w >> 3;
        int c16 = w & 7;
        const __nv_bfloat16* src;
        int grow;
        if (mat == 0)      { src = Ahi; grow = m0 + row; }
        else if (mat == 1) { src = Alo; grow = m0 + row; }
        else if (mat == 2) { src = Bhi; grow = n0 + row; }
        else               { src = Blo; grow = n0 + row; }
        uint32_t off = swz((uint32_t)(row * 128 + c16 * 16));
        CP16(st32 + (mat << 14) + off,
             (const void*)(src + (size_t)grow * K + k0 + c16 * 8));
    }
}

template<bool SILU, bool RESID, bool EMIT, bool WF32>
__global__ __launch_bounds__(256)
void mma_gemm(const __nv_bfloat16* __restrict__ Ahi, const __nv_bfloat16* __restrict__ Alo,
              const __nv_bfloat16* __restrict__ Bhi, const __nv_bfloat16* __restrict__ Blo,
              const float* __restrict__ bias, const float* __restrict__ resid,
              float* __restrict__ C, __nv_bfloat16* __restrict__ Chi, __nv_bfloat16* __restrict__ Clo,
              int M, int N, int K)
{
    extern __shared__ char smem_raw[];
    const uint32_t raw32 = smem_u32(smem_raw);
    const uint32_t base32 = (raw32 + 1023u) & ~1023u;

    const int tid = threadIdx.x;
    const int lane = tid & 31;
    const int wid = tid >> 5;
    const int wm = wid & 3;
    const int wn = wid >> 2;
    const int m0 = blockIdx.y * 128;
    const int n0 = blockIdx.x * 128;

    float acc[2][8][4];
    #pragma unroll
    for (int mt = 0; mt < 2; mt++)
        #pragma unroll
        for (int nt = 0; nt < 8; nt++)
            #pragma unroll
            for (int q = 0; q < 4; q++) acc[mt][nt][q] = 0.f;

    const int NK = K / GBK;
    issue_stage(base32, Ahi, Alo, Bhi, Blo, m0, n0, 0, K, tid);
    CP_COMMIT();

    const uint32_t aoff0 = (uint32_t)((wm * 32 + (lane & 15)) * 128 + ((lane >> 4) & 1) * 16);
    const uint32_t boff0 = (uint32_t)((wn * 64 + (lane & 7) + ((lane >> 4) & 1) * 8) * 128
                                      + ((lane >> 3) & 1) * 16);

    for (int i = 0; i < NK; i++) {
        const uint32_t cur32 = base32 + (uint32_t)(i & 1) * STAGE_BYTES;
        if (i + 1 < NK) {
            issue_stage(base32 + (uint32_t)((i + 1) & 1) * STAGE_BYTES,
                        Ahi, Alo, Bhi, Blo, m0, n0, (i + 1) * GBK, K, tid);
            CP_COMMIT();
            CP_WAIT(1);
        } else {
            CP_WAIT(0);
        }
        __syncthreads();

        #pragma unroll
        for (int ks = 0; ks < 4; ks++) {
            const uint32_t ka = aoff0 + ks * 32;
            const uint32_t kb = boff0 + ks * 32;
            uint32_t ah[2][4], al[2][4], bq[4][4];
            ldsm4(ah[0], cur32 + swz(ka));
            ldsm4(ah[1], cur32 + swz(ka + 16 * 128));
            ldsm4(al[0], cur32 + 16384 + swz(ka));
            ldsm4(al[1], cur32 + 16384 + swz(ka + 16 * 128));
            #pragma unroll
            for (int g = 0; g < 4; g++)
                ldsm4(bq[g], cur32 + 32768 + swz(kb + g * 16 * 128));

            #pragma unroll
            for (int mt = 0; mt < 2; mt++)
                #pragma unroll
                for (int nt = 0; nt < 8; nt++)
                    mma_bf16(acc[mt][nt], ah[mt], &bq[nt >> 1][(nt & 1) * 2]);
            #pragma unroll
            for (int mt = 0; mt < 2; mt++)
                #pragma unroll
                for (int nt = 0; nt < 8; nt++)
                    mma_bf16(acc[mt][nt], al[mt], &bq[nt >> 1][(nt & 1) * 2]);
            #pragma unroll
            for (int g = 0; g < 4; g++)
                ldsm4(bq[g], cur32 + 49152 + swz(kb + g * 16 * 128));
            #pragma unroll
            for (int mt = 0; mt < 2; mt++)
                #pragma unroll
                for (int nt = 0; nt < 8; nt++)
                    mma_bf16(acc[mt][nt], ah[mt], &bq[nt >> 1][(nt & 1) * 2]);
        }
        __syncthreads();
    }

    #pragma unroll
    for (int mt = 0; mt < 2; mt++) {
        #pragma unroll
        for (int half = 0; half < 2; half++) {
            const int row = m0 + wm * 32 + mt * 16 + (lane >> 2) + half * 8;
            #pragma unroll
            for (int nt = 0; nt < 8; nt++) {
                const int col = n0 + wn * 64 + nt * 8 + (lane & 3) * 2;
                float v0 = acc[mt][nt][half * 2]     + bias[col];
                float v1 = acc[mt][nt][half * 2 + 1] + bias[col + 1];
                const size_t o = (size_t)row * N + col;
                if (RESID) { v0 += resid[o]; v1 += resid[o + 1]; }
                if (SILU)  { v0 = v0 / (1.f + expf(-v0)); v1 = v1 / (1.f + expf(-v1)); }
                if (WF32)  { *(float2*)(C + o) = make_float2(v0, v1); }
                if (EMIT) {
                    __nv_bfloat16 h0, l0, h1, l1;
                    split2(v0, h0, l0); split2(v1, h1, l1);
                    *(__nv_bfloat162*)(Chi + o) = __nv_bfloat162(h0, h1);
                    *(__nv_bfloat162*)(Clo + o) = __nv_bfloat162(l0, l1);
                }
            }
        }
    }
}

// ------------------------- row L2-norm scale (+optional hi/lo emit) ---------------
template<bool EMIT>
__global__ __launch_bounds__(256)
void l2norm_kernel(const float* __restrict__ x, const float* __restrict__ w,
                   float* __restrict__ out,
                   __nv_bfloat16* __restrict__ ohi, __nv_bfloat16* __restrict__ olo)
{
    const int row = blockIdx.x;
    const int tid = threadIdx.x;
    const float* xr = x + (size_t)row * DD;

    float4 v = *(const float4*)(xr + tid * 4);
    float ss = v.x*v.x + v.y*v.y + v.z*v.z + v.w*v.w;

    __shared__ float red[8];
    __shared__ float inv_s;
    #pragma unroll
    for (int o = 16; o > 0; o >>= 1) ss += __shfl_xor_sync(0xffffffffu, ss, o);
    if ((tid & 31) == 0) red[tid >> 5] = ss;
    __syncthreads();
    if (tid < 32) {
        float t = (tid < 8) ? red[tid] : 0.f;
        #pragma unroll
        for (int o = 4; o > 0; o >>= 1) t += __shfl_xor_sync(0xffffffffu, t, o);
        if (tid == 0) inv_s = 1.f / (sqrtf(t) + 1e-8f);
    }
    __syncthreads();

    const float inv = inv_s;
    float4 wv = *(const float4*)(w + tid * 4);
    float4 o4 = make_float4(wv.x*v.x*inv, wv.y*v.y*inv, wv.z*v.z*inv, wv.w*v.w*inv);
    *(float4*)(out + (size_t)row * DD + tid * 4) = o4;
    if (EMIT) {
        __nv_bfloat16 h0,l0,h1,l1,h2,l2,h3,l3;
        split2(o4.x,h0,l0); split2(o4.y,h1,l1); split2(o4.z,h2,l2); split2(o4.w,h3,l3);
        size_t ob = (size_t)row * DD + tid * 4;
        *(__nv_bfloat162*)(ohi + ob)     = __nv_bfloat162(h0, h1);
        *(__nv_bfloat162*)(ohi + ob + 2) = __nv_bfloat162(h2, h3);
        *(__nv_bfloat162*)(olo + ob)     = __nv_bfloat162(l0, l1);
        *(__nv_bfloat162*)(olo + ob + 2) = __nv_bfloat162(l2, l3);
    }
}

// ------------------------- RoPE ----------------------------------------------------
__global__ void rope_table_kernel(float* __restrict__ cs, float* __restrict__ sn)
{
    int idx = blockIdx.x * blockDim.x + threadIdx.x;
    if (idx >= SS * 16) return;
    int i = idx & 15, pos = idx >> 4;
    double inv = 1.0 / pow(10000.0, (double)(2*i) / 32.0);
    double ang = (double)pos * inv;
    cs[idx] = (float)cos(ang);
    sn[idx] = (float)sin(ang);
}

// qkv fp32 -> head-major bf16 Q,K (roped) + V
__global__ void rope_bf16_kernel(const float* __restrict__ qkv,
                                 const float* __restrict__ cs, const float* __restrict__ sn,
                                 __nv_bfloat16* __restrict__ qb, __nv_bfloat16* __restrict__ kb,
                                 __nv_bfloat16* __restrict__ vb)
{
    int idx = blockIdx.x * blockDim.x + threadIdx.x;
    if (idx >= BH * SS * 32) return;
    const int d2 = idx & 31;
    const int s  = (idx >> 5) & (SS - 1);
    const int bh = idx >> 16;
    const int b = bh >> 4, h = bh & 15;

    const float* base = qkv + ((size_t)(b*SS + s)) * QKVW + h*192 + 2*d2;
    float2 q = *(const float2*)(base);
    float2 k = *(const float2*)(base + 64);
    float2 v = *(const float2*)(base + 128);
    if (d2 < 16) {
        const float c = cs[s*16 + d2], sv = sn[s*16 + d2];
        q = make_float2(q.x*c - q.y*sv, q.y*c + q.x*sv);
        k = make_float2(k.x*c - k.y*sv, k.y*c + k.x*sv);
    }
    const size_t o = ((size_t)bh*SS + s)*64 + 2*d2;
    *(__nv_bfloat162*)(qb + o) = __floats2bfloat162_rn(q.x, q.y);
    *(__nv_bfloat162*)(kb + o) = __floats2bfloat162_rn(k.x, k.y);
    *(__nv_bfloat162*)(vb + o) = __floats2bfloat162_rn(v.x, v.y);
}

// exact fp32 V column sums per (b,h)
__global__ void vsum_kernel(const float* __restrict__ qkv, float* __restrict__ vsum)
{
    __shared__ float red[4][64];
    const int bh = blockIdx.x;
    const int b = bh >> 4, h = bh & 15;
    const int d = threadIdx.x & 63, p = threadIdx.x >> 6;
    float s = 0.f;
    for (int t = p; t < SS; t += 4)
        s += qkv[((size_t)(b*SS + t)) * QKVW + h*192 + 128 + d];
    red[p][d] = s;
    __syncthreads();
    if (p == 0) vsum[bh*64 + d] = red[0][d] + red[1][d] + red[2][d] + red[3][d];
}

// ------------------------- tensor-core attention (linear log-softmax) -------------
// per CTA: 128 q-rows of one (b,h); 8 warps x 16 rows; 64-key chunks, double buffer.
#define ATT_SMEM (1024 + 48*1024)

__device__ __forceinline__ void issue_kv(uint32_t st,
    const __nv_bfloat16* __restrict__ kbase, const __nv_bfloat16* __restrict__ vbase,
    int t0, int tid)
{
    #pragma unroll
    for (int it = 0; it < 2; it++) {
        int idx = tid + it * 256;            // 0..511
        int row = idx >> 3, c16 = idx & 7;
        uint32_t soff = swz((uint32_t)(row * 128 + c16 * 16));
        CP16(st + soff,        (const void*)(kbase + (size_t)(t0 + row) * 64 + c16 * 8));
        CP16(st + 8192 + soff, (const void*)(vbase + (size_t)(t0 + row) * 64 + c16 * 8));
    }
}

__global__ __launch_bounds__(256)
void attn_mma_kernel(const __nv_bfloat16* __restrict__ qb,
                     const __nv_bfloat16* __restrict__ kb,
                     const __nv_bfloat16* __restrict__ vb,
                     const float* __restrict__ mask,
                     const float* __restrict__ vsum,
                     __nv_bfloat16* __restrict__ aohi,
                     __nv_bfloat16* __restrict__ aolo)
{
    extern __shared__ char sm_raw[];
    const uint32_t raw32 = smem_u32(sm_raw);
    const uint32_t s32 = (raw32 + 1023u) & ~1023u;  // Q at s32, stages at +16K

    const int bh = blockIdx.y;
    const int b = bh >> 4, h = bh & 15;
    const int s0 = blockIdx.x * 128;
    const int tid = threadIdx.x, lane = tid & 31, wid = tid >> 5;

    const __nv_bfloat16* qbase = qb + ((size_t)bh*SS + s0) * 64;
    const __nv_bfloat16* kbase = kb + (size_t)bh*SS*64;
    const __nv_bfloat16* vbase = vb + (size_t)bh*SS*64;

    // Q block 128x64 bf16 -> smem (group 0)
    #pragma unroll
    for (int it = 0; it < 4; it++) {
        int idx = tid + it * 256;            // 0..1023
        int row = idx >> 3, c16 = idx & 7;
        CP16(s32 + swz((uint32_t)(row * 128 + c16 * 16)),
             (const void*)(qbase + (size_t)row * 64 + c16 * 8));
    }
    CP_COMMIT();
    issue_kv(s32 + 16384, kbase, vbase, 0, tid);   // chunk 0 (group 1)
    CP_COMMIT();

    CP_WAIT(1);                                     // Q ready
    __syncthreads();

    // Q fragments: warp owns rows wid*16..+15
    uint32_t qf[4][4];
    #pragma unroll
    for (int ks = 0; ks < 4; ks++)
        ldsm4(qf[ks], s32 + swz((uint32_t)((wid*16 + (lane & 15)) * 128 + ks*32 + (lane >> 4) * 16)));

    float oacc[8][4];
    #pragma unroll
    for (int j = 0; j < 8; j++)
        #pragma unroll
        for (int q = 0; q < 4; q++) oacc[j][q] = 0.f;
    float m0 = -INFINITY, m1 = -INFINITY, l0 = 0.f, l1 = 0.f;

    const float scale = 0.125f;
    const int r = lane >> 2;
    const float* mrow0 = mask + (size_t)b*SS*SS + (size_t)(s0 + wid*16 + r) * SS + (lane & 3) * 2;

    for (int i = 0; i < 32; i++) {
        const uint32_t cur = s32 + 16384 + (uint32_t)(i & 1) * 16384;
        if (i + 1 < 32) {
            issue_kv(s32 + 16384 + (uint32_t)((i + 1) & 1) * 16384, kbase, vbase, (i + 1) * 64, tid);
            CP_COMMIT();
            CP_WAIT(1);
        } else {
            CP_WAIT(0);
        }
        __syncthreads();

        // ---- S = Q @ K^T ----
        float sacc[8][4];
        #pragma unroll
        for (int j = 0; j < 8; j++)
            #pragma unroll
            for (int q = 0; q < 4; q++) sacc[j][q] = 0.f;

        #pragma unroll
        for (int ks = 0; ks < 4; ks++) {
            #pragma unroll
            for (int j = 0; j < 4; j++) {
                uint32_t kf[4];
                ldsm4(kf, cur + swz((uint32_t)((j*16 + (lane >> 4) * 8 + (lane & 7)) * 128
                                               + ks*32 + ((lane >> 3) & 1) * 16)));
                mma_bf16(sacc[2*j],     qf[ks], &kf[0]);
                mma_bf16(sacc[2*j + 1], qf[ks], &kf[2]);
            }
        }

        // ---- scale + mask ----
        const float* mr = mrow0 + i * 64;
        #pragma unroll
        for (int j = 0; j < 8; j++) {
            float2 mk0 = *(const float2*)(mr + j*8);
            float2 mk1 = *(const float2*)(mr + 8*SS + j*8);
            sacc[j][0] = sacc[j][0]*scale + mk0.x;
            sacc[j][1] = sacc[j][1]*scale + mk0.y;
            sacc[j][2] = sacc[j][2]*scale + mk1.x;
            sacc[j][3] = sacc[j][3]*scale + mk1.y;
        }

        // ---- running logsumexp stats (rows r, r+8 within warp) ----
        float tm0 = -INFINITY, tm1 = -INFINITY;
        #pragma unroll
        for (int j = 0; j < 8; j++) {
            tm0 = fmaxf(tm0, fmaxf(sacc[j][0], sacc[j][1]));
            tm1 = fmaxf(tm1, fmaxf(sacc[j][2], sacc[j][3]));
        }
        tm0 = fmaxf(tm0, __shfl_xor_sync(0xffffffffu, tm0, 1));
        tm0 = fmaxf(tm0, __shfl_xor_sync(0xffffffffu, tm0, 2));
        tm1 = fmaxf(tm1, __shfl_xor_sync(0xffffffffu, tm1, 1));
        tm1 = fmaxf(tm1, __shfl_xor_sync(0xffffffffu, tm1, 2));
        const float nm0 = fmaxf(m0, tm0), nm1 = fmaxf(m1, tm1);
        float e0 = 0.f, e1 = 0.f;
        #pragma unroll
        for (int j = 0; j < 8; j++) {
            e0 += __expf(sacc[j][0] - nm0) + __expf(sacc[j][1] - nm0);
            e1 += __expf(sacc[j][2] - nm1) + __expf(sacc[j][3] - nm1);
        }
        e0 += __shfl_xor_sync(0xffffffffu, e0, 1);
        e0 += __shfl_xor_sync(0xffffffffu, e0, 2);
        e1 += __shfl_xor_sync(0xffffffffu, e1, 1);
        e1 += __shfl_xor_sync(0xffffffffu, e1, 2);
        l0 = l0 * __expf(m0 - nm0) + e0;  m0 = nm0;
        l1 = l1 * __expf(m1 - nm1) + e1;  m1 = nm1;

        // ---- S (bf16) @ V: C-frag -> A-frag repack ----
        uint32_t sf[4][4];
        #pragma unroll
        for (int ks = 0; ks < 4; ks++) {
            sf[ks][0] = packbf(sacc[2*ks][0],     sacc[2*ks][1]);
            sf[ks][1] = packbf(sacc[2*ks][2],     sacc[2*ks][3]);
            sf[ks][2] = packbf(sacc[2*ks + 1][0], sacc[2*ks + 1][1]);
            sf[ks][3] = packbf(sacc[2*ks + 1][2], sacc[2*ks + 1][3]);
        }
        const uint32_t vst = cur + 8192;
        #pragma unroll
        for (int ks = 0; ks < 4; ks++) {
            #pragma unroll
            for (int db = 0; db < 4; db++) {
                uint32_t vf[4];
                ldsm4t(vf, vst + swz((uint32_t)((ks*16 + ((lane >> 3) & 1) * 8 + (lane & 7)) * 128
                                                + db*32 + (lane >> 4) * 16)));
                mma_bf16(oacc[2*db],     sf[ks], &vf[0]);
                mma_bf16(oacc[2*db + 1], sf[ks], &vf[2]);
            }
        }
        __syncthreads();
    }

    // ---- epilogue: ao = oacc - lse * vsum ----
    const float lse0 = m0 + logf(l0);
    const float lse1 = m1 + logf(l1);
    const size_t row0 = (size_t)(b*SS + s0 + wid*16 + r);
    #pragma unroll
    for (int j = 0; j < 8; j++) {
        const int dcol = j*8 + (lane & 3) * 2;
        float2 vs = *(const float2*)(vsum + bh*64 + dcol);
        const size_t o0 = row0 * DD + h*64 + dcol;
        const size_t o1 = o0 + 8 * DD;
        float a00 = oacc[j][0] - lse0 * vs.x;
        float a01 = oacc[j][1] - lse0 * vs.y;
        float a10 = oacc[j][2] - lse1 * vs.x;
        float a11 = oacc[j][3] - lse1 * vs.y;
        __nv_bfloat16 h0,l0b,h1,l1b;
        split2(a00, h0, l0b); split2(a01, h1, l1b);
        *(__nv_bfloat162*)(aohi + o0) = __nv_bfloat162(h0, h1);
        *(__nv_bfloat162*)(aolo + o0) = __nv_bfloat162(l0b, l1b);
        split2(a10, h0, l0b); split2(a11, h1, l1b);
        *(__nv_bfloat162*)(aohi + o1) = __nv_bfloat162(h0, h1);
        *(__nv_bfloat162*)(aolo + o1) = __nv_bfloat162(l0b, l1b);
    }
}

// ------------------------- launch -------------------------------------------------
extern "C" void kernel_launch(void* const* d_in, const int* in_sizes, int n_in,
                              void* d_out, int out_size)
{
    const float* x      = (const float*)d_in[0];
    const float* mask   = (const float*)d_in[1];
    const float* Win    = (const float*)d_in[2];
    const float* bin    = (const float*)d_in[3];
    const float* attn_w = (const float*)d_in[4];
    const float* Wqkv   = (const float*)d_in[5];
    const float* bqkv   = (const float*)d_in[6];
    const float* Wout   = (const float*)d_in[7];
    const float* bout   = (const float*)d_in[8];
    const float* W1     = (const float*)d_in[9];
    const float* b1     = (const float*)d_in[10];
    const float* W2     = (const float*)d_in[11];
    const float* b2     = (const float*)d_in[12];
    const float* ffn_w  = (const float*)d_in[13];
    float* out = (float*)d_out;

    float *h, *h2, *t, *qkv, *cs, *sn, *vsum;
    cudaGetSymbolAddress((void**)&h,    g_h);
    cudaGetSymbolAddress((void**)&h2,   g_h2);
    cudaGetSymbolAddress((void**)&t,    g_t);
    cudaGetSymbolAddress((void**)&qkv,  g_qkv);
    cudaGetSymbolAddress((void**)&cs,   g_cs);
    cudaGetSymbolAddress((void**)&sn,   g_sn);
    cudaGetSymbolAddress((void**)&vsum, g_vsum);

    __nv_bfloat16 *xhi,*xlo,*hhi,*hlo,*aohi,*aolo,*h2hi,*h2lo,*thi,*tlo,*qb,*kb,*vb;
    __nv_bfloat16 *winThi,*winTlo,*wqkvThi,*wqkvTlo,*woutThi,*woutTlo,*w1Thi,*w1Tlo,*w2Thi,*w2Tlo;
    cudaGetSymbolAddress((void**)&xhi, g_xhi);   cudaGetSymbolAddress((void**)&xlo, g_xlo);
    cudaGetSymbolAddress((void**)&hhi, g_hhi);   cudaGetSymbolAddress((void**)&hlo, g_hlo);
    cudaGetSymbolAddress((void**)&aohi, g_aohi); cudaGetSymbolAddress((void**)&aolo, g_aolo);
    cudaGetSymbolAddress((void**)&h2hi, g_h2hi); cudaGetSymbolAddress((void**)&h2lo, g_h2lo);
    cudaGetSymbolAddress((void**)&thi, g_thi);   cudaGetSymbolAddress((void**)&tlo, g_tlo);
    cudaGetSymbolAddress((void**)&qb, g_qb);
    cudaGetSymbolAddress((void**)&kb, g_kb);
    cudaGetSymbolAddress((void**)&vb, g_vb);
    cudaGetSymbolAddress((void**)&winThi, g_winThi);   cudaGetSymbolAddress((void**)&winTlo, g_winTlo);
    cudaGetSymbolAddress((void**)&wqkvThi, g_wqkvThi); cudaGetSymbolAddress((void**)&wqkvTlo, g_wqkvTlo);
    cudaGetSymbolAddress((void**)&woutThi, g_woutThi); cudaGetSymbolAddress((void**)&woutTlo, g_woutTlo);
    cudaGetSymbolAddress((void**)&w1Thi, g_w1Thi);     cudaGetSymbolAddress((void**)&w1Tlo, g_w1Tlo);
    cudaGetSymbolAddress((void**)&w2Thi, g_w2Thi);     cudaGetSymbolAddress((void**)&w2Tlo, g_w2Tlo);

    cudaFuncSetAttribute(mma_gemm<false,false,false,true>, cudaFuncAttributeMaxDynamicSharedMemorySize, GEMM_SMEM);
    cudaFuncSetAttribute(mma_gemm<false,true, true, true>, cudaFuncAttributeMaxDynamicSharedMemorySize, GEMM_SMEM);
    cudaFuncSetAttribute(mma_gemm<true, false,true, false>,cudaFuncAttributeMaxDynamicSharedMemorySize, GEMM_SMEM);
    cudaFuncSetAttribute(mma_gemm<false,true, false,true>, cudaFuncAttributeMaxDynamicSharedMemorySize, GEMM_SMEM);
    cudaFuncSetAttribute(attn_mma_kernel, cudaFuncAttributeMaxDynamicSharedMemorySize, ATT_SMEM);

    // --- weight & input converts ---
    conv_hilo_kernel<<<(RR*DD/4 + 255)/256, 256>>>((const float4*)x, (__nv_bfloat162*)xhi, (__nv_bfloat162*)xlo, RR*DD/4);
    convT_kernel<<<dim3(DD/32,  DD/32), dim3(32,8)>>>(Win,  winThi,  winTlo,  DD, DD);
    convT_kernel<<<dim3(QKVW/32,DD/32), dim3(32,8)>>>(Wqkv, wqkvThi, wqkvTlo, DD, QKVW);
    convT_kernel<<<dim3(DD/32,  DD/32), dim3(32,8)>>>(Wout, woutThi, woutTlo, DD, DD);
    convT_kernel<<<dim3(DD/32,  DD/32), dim3(32,8)>>>(W1,   w1Thi,   w1Tlo,   DD, DD);
    convT_kernel<<<dim3(DD/32,  DD/32), dim3(32,8)>>>(W2,   w2Thi,   w2Tlo,   DD, DD);
    rope_table_kernel<<<(SS*16 + 255)/256, 256>>>(cs, sn);

    const dim3 gD(DD/128, RR/128);
    const dim3 gQ(QKVW/128, RR/128);

    // 1) t = x @ Win + bin
    mma_gemm<false,false,false,true><<<gD, 256, GEMM_SMEM>>>(xhi, xlo, winThi, winTlo, bin, nullptr,
                                                             t, nullptr, nullptr, RR, DD, DD);
    // 2) h = l2norm_scale(t) (+ emit hi/lo)
    l2norm_kernel<true><<<RR, 256>>>(t, attn_w, h, hhi, hlo);
    // 3) qkv = h @ Wqkv + bqkv
    mma_gemm<false,false,false,true><<<gQ, 256, GEMM_SMEM>>>(hhi, hlo, wqkvThi, wqkvTlo, bqkv, nullptr,
                                                             qkv, nullptr, nullptr, RR, QKVW, DD);
    // 4) RoPE + bf16 repack + exact vsum
    rope_bf16_kernel<<<(BH*SS*32 + 255)/256, 256>>>(qkv, cs, sn, qb, kb, vb);
    vsum_kernel<<<BH, 256>>>(qkv, vsum);
    // 5) tensor-core attention -> aohi/aolo
    attn_mma_kernel<<<dim3(SS/128, BH), 256, ATT_SMEM>>>(qb, kb, vb, mask, vsum, aohi, aolo);
    // 6) h2 = h + (ao @ Wout + bout) (+ emit)
    mma_gemm<false,true,true,true><<<gD, 256, GEMM_SMEM>>>(aohi, aolo, woutThi, woutTlo, bout, h,
                                                           h2, h2hi, h2lo, RR, DD, DD);
    // 7) t = silu(h2 @ W1 + b1) (emit only)
    mma_gemm<true,false,true,false><<<gD, 256, GEMM_SMEM>>>(h2hi, h2lo, w1Thi, w1Tlo, b1, nullptr,
                                                            nullptr, thi, tlo, RR, DD, DD);
    // 8) h = h2 + (t @ W2 + b2)
    mma_gemm<false,true,false,true><<<gD, 256, GEMM_SMEM>>>(thi, tlo, w2Thi, w2Tlo, b2, h2,
                                                            h, nullptr, nullptr, RR, DD, DD);
    // 9) out = l2norm_scale(h, ffn_norm_w)
    l2norm_kernel<false><<<RR, 256>>>(h, ffn_w, out, nullptr, nullptr);
}